// round 15
// baseline (speedup 1.0000x reference)
#include <cuda_runtime.h>
#include <math.h>

#define B_   8
#define T_   256
#define MEL_ 128
#define D_   192
#define NC_  20
#define D2_  384
#define NT_  32
#define ND_  4
#define EPS_ 1e-5f

__device__ float g_xp [B_*T_*D_];
__device__ float g_x2 [B_*T_*D_];
__device__ float g_h  [B_*T_*D_];
__device__ float g_g2 [B_*T_*D_];
__device__ float g_x3 [B_*T_*D_];
__device__ float g_Kd [B_*ND_*D_];
__device__ float g_Vd [B_*ND_*D_];
__device__ float g_Qd [B_*ND_*D_];
__device__ float g_Ed [B_*ND_*D_];
__device__ float g_Fd [B_*ND_*D_];
__device__ float g_Kt [B_*NT_*D_];
__device__ float g_Vt [B_*NT_*D_];
__device__ float g_Qt [B_*NT_*D_];
__device__ float g_Et [B_*NT_*D_];
__device__ float g_Wao [D_*D_];
__device__ float g_bao [D_];
__device__ float g_Wkqd[D_*D_];
__device__ float g_Wkqt[D_*D_];
__device__ float g_pp [B_*16*D_];

__device__ __forceinline__ float cdv(int d) {
    const float L2A = -0.014499569695115089f;   // log2(0.99)
    const float L2E = -0.152003093445049970f;   // log2(0.90)
    float n = (float)(d + 1);
    return (exp2f(n * L2A) - exp2f(n * L2E)) * (0.1f / 0.09f);
}

// =================== 3xTF32 warp-MMA GEMM machinery ===================
#define AS_STRIDE 196        // 192 + 4 pad
#define WS_STRIDE 72         // 64 + 8 pad
#define PLANE_A (64 * AS_STRIDE)     // 12544 words per plane
#define PLANE_W (192 * WS_STRIDE)    // 13824 words per plane

__device__ __forceinline__ unsigned f2tf(float v) {
    unsigned r; asm("cvt.rna.tf32.f32 %0, %1;" : "=r"(r) : "f"(v)); return r;
}
__device__ __forceinline__ void mma8(float c[4], unsigned a0, unsigned a1, unsigned a2,
                                     unsigned a3, unsigned b0, unsigned b1) {
    asm("mma.sync.aligned.m16n8k8.row.col.f32.tf32.tf32.f32 "
        "{%0,%1,%2,%3},{%4,%5,%6,%7},{%8,%9},{%0,%1,%2,%3};"
        : "+f"(c[0]), "+f"(c[1]), "+f"(c[2]), "+f"(c[3])
        : "r"(a0), "r"(a1), "r"(a2), "r"(a3), "r"(b0), "r"(b1));
}
__device__ __forceinline__ void split2(float v, unsigned& hi, unsigned& lo) {
    hi = f2tf(v);
    lo = f2tf(v - __uint_as_float(hi));
}
// A planes: Ahi/Alo [row*196 + k], 64 rows
__device__ __forceinline__ void fillA3(unsigned* Ahi, unsigned* Alo,
                                       const float* __restrict__ A, int ldA, int m0, int K) {
    int tid = threadIdx.x;
    int kq = K >> 2;
    for (int idx = tid; idx < 64 * kq; idx += 256) {
        int r = idx / kq, c4 = idx - r * kq;
        float4 v = *(const float4*)&A[(size_t)(m0 + r) * ldA + c4 * 4];
        uint4 h, l;
        split2(v.x, h.x, l.x); split2(v.y, h.y, l.y);
        split2(v.z, h.z, l.z); split2(v.w, h.w, l.w);
        *(uint4*)&Ahi[r * AS_STRIDE + c4 * 4] = h;
        *(uint4*)&Alo[r * AS_STRIDE + c4 * 4] = l;
    }
}
// W planes: Whi/Wlo [k*72 + col], cols from (W + col0), ldW
__device__ __forceinline__ void fillW3(unsigned* Whi, unsigned* Wlo,
                                       const float* __restrict__ W, int ldW, int col0, int K) {
    int tid = threadIdx.x;
    for (int idx = tid; idx < K * 16; idx += 256) {
        int k = idx >> 4, c4 = idx & 15;
        float4 v = *(const float4*)&W[(size_t)k * ldW + col0 + c4 * 4];
        uint4 h, l;
        split2(v.x, h.x, l.x); split2(v.y, h.y, l.y);
        split2(v.z, h.z, l.z); split2(v.w, h.w, l.w);
        *(uint4*)&Whi[k * WS_STRIDE + c4 * 4] = h;
        *(uint4*)&Wlo[k * WS_STRIDE + c4 * 4] = l;
    }
}
// warp w: rows (w&3)*16, cols (w>>2)*32 of 64x64 tile; 3xTF32 accumulate
__device__ __forceinline__ void mma_core3(const unsigned* Ahi, const unsigned* Alo,
                                          const unsigned* Whi, const unsigned* Wlo,
                                          int K, float acc[4][4], int w, int lane) {
    int gid = lane >> 2, tig = lane & 3;
    int wr0 = (w & 3) * 16, wc0 = (w >> 2) * 32;
    for (int ks = 0; ks < K; ks += 8) {
        int i00 = (wr0 + gid) * AS_STRIDE + ks + tig;
        int i10 = (wr0 + gid + 8) * AS_STRIDE + ks + tig;
        unsigned ah0 = Ahi[i00], ah1 = Ahi[i10], ah2 = Ahi[i00 + 4], ah3 = Ahi[i10 + 4];
        unsigned al0 = Alo[i00], al1 = Alo[i10], al2 = Alo[i00 + 4], al3 = Alo[i10 + 4];
#pragma unroll
        for (int j = 0; j < 4; j++) {
            int b0i = (ks + tig) * WS_STRIDE + wc0 + j * 8 + gid;
            int b1i = (ks + tig + 4) * WS_STRIDE + wc0 + j * 8 + gid;
            unsigned bh0 = Whi[b0i], bh1 = Whi[b1i];
            unsigned bl0 = Wlo[b0i], bl1 = Wlo[b1i];
            mma8(acc[j], ah0, ah1, ah2, ah3, bh0, bh1);
            mma8(acc[j], ah0, ah1, ah2, ah3, bl0, bl1);
            mma8(acc[j], al0, al1, al2, al3, bh0, bh1);
        }
    }
}

// ---------------- generic 3xTF32 GEMM: C = A@W (+bias)(+res) ----------------
__global__ void __launch_bounds__(256) mma_gemm(
    float* __restrict__ C, const float* __restrict__ A, const float* __restrict__ W,
    const float* __restrict__ bias, const float* __restrict__ res, int ldA, int K)
{
    extern __shared__ __align__(16) unsigned sh[];
    unsigned* Ahi = sh;
    unsigned* Alo = sh + PLANE_A;
    unsigned* Whi = sh + 2 * PLANE_A;
    unsigned* Wlo = Whi + PLANE_W;
    int blk = blockIdx.x;
    int m0 = (blk / 3) * 64, n0 = (blk % 3) * 64;
    int tid = threadIdx.x, w = tid >> 5, lane = tid & 31;
    fillA3(Ahi, Alo, A, ldA, m0, K);
    fillW3(Whi, Wlo, W, D_, n0, K);
    __syncthreads();
    float acc[4][4] = {};
    mma_core3(Ahi, Alo, Whi, Wlo, K, acc, w, lane);
    int gid = lane >> 2, tig = lane & 3;
    int wr0 = (w & 3) * 16, wc0 = (w >> 2) * 32;
#pragma unroll
    for (int j = 0; j < 4; j++) {
        int col = n0 + wc0 + j * 8 + 2 * tig;
        int r0 = m0 + wr0 + gid, r1 = r0 + 8;
        float b0 = bias ? bias[col] : 0.f, b1 = bias ? bias[col + 1] : 0.f;
        float2 o0 = { acc[j][0] + b0, acc[j][1] + b1 };
        float2 o1 = { acc[j][2] + b0, acc[j][3] + b1 };
        if (res) {
            float2 v0 = *(const float2*)&res[(size_t)r0 * D_ + col];
            float2 v1 = *(const float2*)&res[(size_t)r1 * D_ + col];
            o0.x += v0.x; o0.y += v0.y; o1.x += v1.x; o1.y += v1.y;
        }
        *(float2*)&C[(size_t)r0 * D_ + col] = o0;
        *(float2*)&C[(size_t)r1 * D_ + col] = o1;
    }
}

// ---------------- x2 3xTF32 GEMM: x2 = xp + xp@Wao + bao + alpha@F ----------------
__global__ void __launch_bounds__(256) mma_x2(
    float* __restrict__ x2, const float* __restrict__ xp,
    const float* __restrict__ Wao, const float* __restrict__ bao,
    const float* __restrict__ Qd, const float* __restrict__ Fd)
{
    extern __shared__ __align__(16) unsigned sh[];
    unsigned* Ahi = sh;
    unsigned* Alo = sh + PLANE_A;
    unsigned* Whi = sh + 2 * PLANE_A;
    unsigned* Wlo = Whi + PLANE_W;
    float* sQ   = (float*)(Wlo + PLANE_W);
    float* sF   = sQ + ND_ * D_;
    float* alph = sF + ND_ * D_;   // [64][4]
    int blk = blockIdx.x;
    int m0 = (blk / 3) * 64, n0 = (blk % 3) * 64;
    int b = m0 >> 8;
    int tid = threadIdx.x, w = tid >> 5, lane = tid & 31;
    fillA3(Ahi, Alo, xp, D_, m0, D_);
    fillW3(Whi, Wlo, Wao, D_, n0, D_);
    for (int idx = tid; idx < ND_ * D_; idx += 256) {
        sQ[idx] = Qd[(size_t)b * ND_ * D_ + idx];
        sF[idx] = Fd[(size_t)b * ND_ * D_ + idx];
    }
    __syncthreads();
    float acc[4][4] = {};
    mma_core3(Ahi, Alo, Whi, Wlo, D_, acc, w, lane);
    // alpha: thread (row = tid>>2, j = tid&3), xp reconstructed hi+lo
    {
        int row = tid >> 2, j = tid & 3;
        const float* qj = &sQ[j * D_];
        const unsigned* ah = &Ahi[row * AS_STRIDE];
        const unsigned* al = &Alo[row * AS_STRIDE];
        float s0 = 0.f, s1 = 0.f;
#pragma unroll 8
        for (int k = 0; k < D_; k += 2) {
            float v0 = __uint_as_float(ah[k])     + __uint_as_float(al[k]);
            float v1 = __uint_as_float(ah[k + 1]) + __uint_as_float(al[k + 1]);
            s0 = fmaf(v0, qj[k],     s0);
            s1 = fmaf(v1, qj[k + 1], s1);
        }
        float s = s0 + s1;
        int t = (m0 + row) & (T_ - 1), r = t >> 6;
        alph[row * 4 + j] = (j <= r) ? 0.5f * cdv(r - j) * s : 0.f;
    }
    __syncthreads();
    int gid = lane >> 2, tig = lane & 3;
    int wr0 = (w & 3) * 16, wc0 = (w >> 2) * 32;
#pragma unroll
    for (int j = 0; j < 4; j++) {
        int col = n0 + wc0 + j * 8 + 2 * tig;
        int lr0 = wr0 + gid, lr1 = lr0 + 8;
        int r0 = m0 + lr0, r1 = m0 + lr1;
        float2 v0 = *(const float2*)&xp[(size_t)r0 * D_ + col];
        float2 v1 = *(const float2*)&xp[(size_t)r1 * D_ + col];
        float o00 = acc[j][0] + bao[col] + v0.x;
        float o01 = acc[j][1] + bao[col + 1] + v0.y;
        float o10 = acc[j][2] + bao[col] + v1.x;
        float o11 = acc[j][3] + bao[col + 1] + v1.y;
#pragma unroll
        for (int jj = 0; jj < ND_; jj++) {
            float f0 = sF[jj * D_ + col], f1 = sF[jj * D_ + col + 1];
            float a0 = alph[lr0 * 4 + jj], a1 = alph[lr1 * 4 + jj];
            o00 = fmaf(a0, f0, o00); o01 = fmaf(a0, f1, o01);
            o10 = fmaf(a1, f0, o10); o11 = fmaf(a1, f1, o11);
        }
        float2 w0 = {o00, o01}, w1 = {o10, o11};
        *(float2*)&x2[(size_t)r0 * D_ + col] = w0;
        *(float2*)&x2[(size_t)r1 * D_ + col] = w1;
    }
}

// ---------------- glu 3xTF32 (two W halves sequentially) + GLU/dw/BN/SiLU ----------------
__global__ void __launch_bounds__(256) mma_glu(
    float* __restrict__ outp, const float* __restrict__ A, const float* __restrict__ W,
    const float* __restrict__ bias,
    const float* __restrict__ dw, const float* __restrict__ db,
    const float* __restrict__ bs, const float* __restrict__ bb)
{
    extern __shared__ __align__(16) unsigned sh[];
    unsigned* Ahi = sh;
    unsigned* Alo = sh + PLANE_A;
    unsigned* Whi = sh + 2 * PLANE_A;
    unsigned* Wlo = Whi + PLANE_W;
    int blk = blockIdx.x;
    int m0 = (blk / 3) * 64, n0 = (blk % 3) * 64;
    int tid = threadIdx.x, w = tid >> 5, lane = tid & 31;
    fillA3(Ahi, Alo, A, D_, m0, D_);
    fillW3(Whi, Wlo, W, D2_, n0, D_);          // a-half
    __syncthreads();
    float cA[4][4] = {}, cG[4][4] = {};
    mma_core3(Ahi, Alo, Whi, Wlo, D_, cA, w, lane);
    __syncthreads();
    fillW3(Whi, Wlo, W, D2_, D_ + n0, D_);     // g-half
    __syncthreads();
    mma_core3(Ahi, Alo, Whi, Wlo, D_, cG, w, lane);
    int gid = lane >> 2, tig = lane & 3;
    int wr0 = (w & 3) * 16, wc0 = (w >> 2) * 32;
#pragma unroll
    for (int j = 0; j < 4; j++) {
        int col = n0 + wc0 + j * 8 + 2 * tig;
        int r0 = m0 + wr0 + gid, r1 = r0 + 8;
#pragma unroll
        for (int half = 0; half < 2; half++) {
            int row = half ? r1 : r0;
            float va = (half ? cA[j][2] : cA[j][0]);
            float vb = (half ? cA[j][3] : cA[j][1]);
            float ga = (half ? cG[j][2] : cG[j][0]);
            float gb = (half ? cG[j][3] : cG[j][1]);
            float2 o;
#pragma unroll
            for (int u = 0; u < 2; u++) {
                int cc = col + u;
                float a = (u ? vb : va) + bias[cc];
                float g = (u ? gb : ga) + bias[D_ + cc];
                float h = a * (1.f / (1.f + expf(-g)));
                h = h * dw[cc] + db[cc];
                h = h * bs[cc] + bb[cc];
                h = h * (1.f / (1.f + expf(-h)));
                (u ? o.y : o.x) = h;
            }
            *(float2*)&outp[(size_t)row * D_ + col] = o;
        }
    }
}

// =================== fp32 pieces (R8 bodies) ===================
__device__ __forceinline__ void dev_gemm_tile(float* sh,
    const float* __restrict__ A, int ldA, const float* __restrict__ W, int ldW, bool transB,
    const float* __restrict__ bias, const float* __restrict__ res, float* __restrict__ C, int ldC,
    int m0, int n0, int K)
{
    float (*As)[68] = (float (*)[68])sh;
    float (*Ws)[64] = (float (*)[64])(sh + 16 * 68);
    int tid = threadIdx.x;
    int tx = tid & 15, ty = tid >> 4;
    float c[4][4] = {};
    for (int k0 = 0; k0 < K; k0 += 16) {
        {
            int arow = tid >> 2, acol = (tid & 3) * 4;
            float4 v = *(const float4*)&A[(size_t)(m0 + arow) * ldA + k0 + acol];
            As[acol + 0][arow] = v.x; As[acol + 1][arow] = v.y;
            As[acol + 2][arow] = v.z; As[acol + 3][arow] = v.w;
        }
        {
            int wrow = tid >> 4, wcol = (tid & 15) * 4;
            if (transB) {
#pragma unroll
                for (int u = 0; u < 4; u++)
                    Ws[wrow][wcol + u] = W[(size_t)(n0 + wcol + u) * ldW + k0 + wrow];
            } else {
                *(float4*)&Ws[wrow][wcol] = *(const float4*)&W[(size_t)(k0 + wrow) * ldW + n0 + wcol];
            }
        }
        __syncthreads();
#pragma unroll
        for (int kk = 0; kk < 16; kk++) {
            float4 af = *(const float4*)&As[kk][ty * 4];
            float4 bf = *(const float4*)&Ws[kk][tx * 4];
            float a4[4] = {af.x, af.y, af.z, af.w};
            float b4[4] = {bf.x, bf.y, bf.z, bf.w};
#pragma unroll
            for (int i = 0; i < 4; i++)
#pragma unroll
                for (int j = 0; j < 4; j++) c[i][j] = fmaf(a4[i], b4[j], c[i][j]);
        }
        __syncthreads();
    }
#pragma unroll
    for (int i = 0; i < 4; i++) {
        int row = m0 + ty * 4 + i, col = n0 + tx * 4;
        float4 o; float* po = &o.x;
#pragma unroll
        for (int j = 0; j < 4; j++) {
            float v = c[i][j];
            if (bias) v += bias[col + j];
            if (res)  v += res[(size_t)row * ldC + col + j];
            po[j] = v;
        }
        *(float4*)&C[(size_t)row * ldC + col] = o;
    }
}

__global__ void __launch_bounds__(256) folds_kernel(
    const float* __restrict__ Wv_a, const float* __restrict__ Wo_a,
    const float* __restrict__ bv_a, const float* __restrict__ bo_a,
    const float* __restrict__ Wk_d, const float* __restrict__ Wq_d,
    const float* __restrict__ Wk_t, const float* __restrict__ Wq_t)
{
    __shared__ __align__(16) float sh[16 * 68 + 16 * 64];
    int blk = blockIdx.x, tid = threadIdx.x;
    if (blk < 9) {
        dev_gemm_tile(sh, Wv_a, D_, Wo_a, D_, false, nullptr, nullptr, g_Wao, D_,
                      (blk / 3) * 64, (blk % 3) * 64, D_);
    } else if (blk < 18) {
        int p = blk - 9;
        dev_gemm_tile(sh, Wk_d, D_, Wq_d, D_, true, nullptr, nullptr, g_Wkqd, D_,
                      (p / 3) * 64, (p % 3) * 64, D_);
    } else if (blk < 27) {
        int p = blk - 18;
        dev_gemm_tile(sh, Wk_t, D_, Wq_t, D_, true, nullptr, nullptr, g_Wkqt, D_,
                      (p / 3) * 64, (p % 3) * 64, D_);
    } else {
        if (tid < D_) {
            float s = bo_a[tid];
#pragma unroll 8
            for (int e = 0; e < D_; e++) s = fmaf(bv_a[e], Wo_a[e * D_ + tid], s);
            g_bao[tid] = s;
        }
    }
}

__global__ void __launch_bounds__(192) projKVQ(
    float* __restrict__ Ko, float* __restrict__ Vo, float* __restrict__ Qo,
    const float* __restrict__ A, const float* __restrict__ Wk,
    const float* __restrict__ Wv, const float* __restrict__ Wkq, int nUpd, int chunk)
{
    __shared__ float sa[D_];
    int blk = blockIdx.x;
    int b = blk / nUpd, i = blk % nUpd;
    int tid = threadIdx.x;
    sa[tid] = A[(size_t)(b * T_ + i * chunk) * D_ + tid];
    __syncthreads();
    if (tid < 144) {
        int gsel = tid / 48, q = tid % 48;
        const float* W = (gsel == 0) ? Wk : (gsel == 1) ? Wv : Wkq;
        float ax = 0.f, ay = 0.f, az = 0.f, aw = 0.f;
#pragma unroll 16
        for (int kk = 0; kk < D_; kk++) {
            float a = sa[kk];
            float4 wv = *(const float4*)&W[kk * D_ + 4 * q];
            ax = fmaf(a, wv.x, ax); ay = fmaf(a, wv.y, ay);
            az = fmaf(a, wv.z, az); aw = fmaf(a, wv.w, aw);
        }
        float* O = (gsel == 0) ? Ko : (gsel == 1) ? Vo : Qo;
        float4 o = {ax, ay, az, aw};
        *(float4*)&O[(size_t)blk * D_ + 4 * q] = o;
    }
}

__global__ void __launch_bounds__(256) rec_d_kernel(
    float* __restrict__ ERR, float* __restrict__ F,
    const float* __restrict__ Kmat, const float* __restrict__ Vmat,
    const float* __restrict__ Wao)
{
    __shared__ float sK[ND_][D_ + 1];
    __shared__ float sE[ND_][D_];
    __shared__ float Acf[ND_][ND_];
    int b = blockIdx.x, tid = threadIdx.x;
    for (int idx = tid; idx < ND_ * D_; idx += 256)
        sK[idx / D_][idx % D_] = Kmat[(size_t)b * ND_ * D_ + idx];
    __syncthreads();
    if (tid < 6) {
        const int pi[6] = {1, 2, 2, 3, 3, 3};
        const int pj[6] = {0, 0, 1, 0, 1, 2};
        int i = pi[tid], j = pj[tid];
        float s0 = 0.f, s1 = 0.f;
#pragma unroll 8
        for (int kk = 0; kk < D_; kk += 2) {
            s0 = fmaf(sK[j][kk],     sK[i][kk],     s0);
            s1 = fmaf(sK[j][kk + 1], sK[i][kk + 1], s1);
        }
        Acf[j][i] = cdv(i - 1 - j) * (s0 + s1);
    }
    __syncthreads();
    if (tid < D_) {
        float err[ND_];
#pragma unroll
        for (int i = 0; i < ND_; i++) {
            float s = Vmat[(size_t)(b * ND_ + i) * D_ + tid];
#pragma unroll
            for (int j = 0; j < i; j++) s -= Acf[j][i] * err[j];
            err[i] = s;
            sE[i][tid] = s;
            ERR[(size_t)(b * ND_ + i) * D_ + tid] = s;
        }
    }
    __syncthreads();
    if (tid < 192) {
        int j = tid / 48, q = tid % 48;
        float4 acc = *(float4*)&sE[j][4 * q];
#pragma unroll 8
        for (int e = 0; e < D_; e++) {
            float a = sE[j][e];
            float4 wv = *(const float4*)&Wao[e * D_ + 4 * q];
            acc.x = fmaf(a, wv.x, acc.x); acc.y = fmaf(a, wv.y, acc.y);
            acc.z = fmaf(a, wv.z, acc.z); acc.w = fmaf(a, wv.w, acc.w);
        }
        *(float4*)&F[(size_t)(b * ND_ + j) * D_ + 4 * q] = acc;
    }
}

__global__ void __launch_bounds__(192) ln_kernel(
    float* __restrict__ outp, const float* __restrict__ in,
    const float* __restrict__ g, const float* __restrict__ bta)
{
    __shared__ float red[2][6];
    int row = blockIdx.x, e = threadIdx.x;
    float v = in[(size_t)row * D_ + e];
    float s = v, s2 = v * v;
#pragma unroll
    for (int o = 16; o > 0; o >>= 1) {
        s  += __shfl_xor_sync(~0u, s,  o);
        s2 += __shfl_xor_sync(~0u, s2, o);
    }
    int w = e >> 5, l = e & 31;
    if (l == 0) { red[0][w] = s; red[1][w] = s2; }
    __syncthreads();
    float ts = 0.f, ts2 = 0.f;
#pragma unroll
    for (int i = 0; i < 6; i++) { ts += red[0][i]; ts2 += red[1][i]; }
    float m = ts / D_;
    float var = ts2 / D_ - m * m;
    outp[(size_t)row * D_ + e] = (v - m) * rsqrtf(var + EPS_) * g[e] + bta[e];
}

__global__ void __launch_bounds__(256) rec_t_kernel(
    float* __restrict__ ERR, const float* __restrict__ Kmat, const float* __restrict__ Vmat)
{
    __shared__ float sK[NT_][D_ + 1];
    __shared__ float Acf[NT_][NT_];
    __shared__ float cd[NT_];
    int b = blockIdx.x, tid = threadIdx.x;
    if (tid < NT_) cd[tid] = cdv(tid);
    for (int idx = tid; idx < NT_ * D_; idx += 256)
        sK[idx / D_][idx % D_] = Kmat[(size_t)b * NT_ * D_ + idx];
    __syncthreads();
    const int NP = NT_ * (NT_ - 1) / 2;
    for (int p = tid; p < NP; p += 256) {
        int i = (int)((1.0f + sqrtf(1.0f + 8.0f * (float)p)) * 0.5f);
        while (i * (i - 1) / 2 > p) i--;
        while ((i + 1) * i / 2 <= p) i++;
        int j = p - i * (i - 1) / 2;
        float s0 = 0.f, s1 = 0.f;
#pragma unroll 8
        for (int kk = 0; kk < D_; kk += 2) {
            s0 = fmaf(sK[j][kk],     sK[i][kk],     s0);
            s1 = fmaf(sK[j][kk + 1], sK[i][kk + 1], s1);
        }
        Acf[j][i] = cd[i - 1 - j] * (s0 + s1);
    }
    __syncthreads();
    if (tid < D_) {
        float err[NT_];
#pragma unroll
        for (int i = 0; i < NT_; i++) {
            float a0 = 0.f, a1 = 0.f;
#pragma unroll
            for (int j = 0; j < i; j++) {
                if (j & 1) a1 = fmaf(Acf[j][i], err[j], a1);
                else       a0 = fmaf(Acf[j][i], err[j], a0);
            }
            err[i] = Vmat[(size_t)(b * NT_ + i) * D_ + tid] - a0 - a1;
            ERR[(size_t)(b * NT_ + i) * D_ + tid] = err[i];
        }
    }
}

__global__ void __launch_bounds__(192) qkfinal(
    const float* __restrict__ x3, const float* __restrict__ Kt, const float* __restrict__ Et,
    const float* __restrict__ g2, const float* __restrict__ b2, float* __restrict__ pp)
{
    extern __shared__ __align__(16) float shq[];
    float (*sKT)[33] = (float (*)[33])shq;
    float* sEt = shq + 192 * 33;
    float* red = sEt + NT_ * D_;
    float* alpha = red + 192;
    float* cd = alpha + 32;
    float* lred = cd + 32;
    int blk = blockIdx.x;
    int b = blk >> 4, tc = blk & 15, t0 = tc * 16;
    int tid = threadIdx.x;
    if (tid < NT_) cd[tid] = cdv(tid);
    for (int idx = tid; idx < NT_ * D_; idx += 192) {
        int j = idx / D_, e = idx % D_;
        sKT[e][j] = Kt[(size_t)(b * NT_ + j) * D_ + e];
        sEt[idx] = Et[(size_t)b * NT_ * D_ + idx];
    }
    __syncthreads();
    int j = tid & 31, g = tid >> 5;
    float ps = 0.f;
    for (int tt = 0; tt < 16; tt++) {
        int t = t0 + tt, row = b * T_ + t, r = t >> 3;
        {
            const float* qr = x3 + (size_t)row * D_;
            float part = 0.f;
#pragma unroll
            for (int u = 0; u < 32; u++) part = fmaf(qr[g * 32 + u], sKT[g * 32 + u][j], part);
            red[j * 6 + g] = part;
        }
        __syncthreads();
        if (tid < NT_) {
            float s = 0.f;
#pragma unroll
            for (int gg = 0; gg < 6; gg++) s += red[tid * 6 + gg];
            alpha[tid] = (tid <= r) ? cd[r - tid] * s : 0.f;
        }
        __syncthreads();
        float s = 0.f;
        for (int jj = 0; jj <= r; jj++) s = fmaf(alpha[jj], sEt[jj * D_ + tid], s);
        float x4 = x3[(size_t)row * D_ + tid] + 0.5f * s;
        float sm = x4, s2 = x4 * x4;
#pragma unroll
        for (int o = 16; o > 0; o >>= 1) {
            sm += __shfl_xor_sync(~0u, sm, o);
            s2 += __shfl_xor_sync(~0u, s2, o);
        }
        if ((tid & 31) == 0) { lred[tid >> 5] = sm; lred[6 + (tid >> 5)] = s2; }
        __syncthreads();
        float ts = 0.f, ts2 = 0.f;
#pragma unroll
        for (int i = 0; i < 6; i++) { ts += lred[i]; ts2 += lred[6 + i]; }
        float m = ts / D_;
        float var = ts2 / D_ - m * m;
        ps += (x4 - m) * rsqrtf(var + EPS_) * g2[tid] + b2[tid];
        __syncthreads();
    }
    pp[(size_t)(b * 16 + tc) * D_ + tid] = ps;
}

__global__ void __launch_bounds__(192) poolcls(
    const float* __restrict__ pp, const float* __restrict__ Wc,
    const float* __restrict__ bc, float* __restrict__ out)
{
    __shared__ float pooled[D_];
    int b = blockIdx.x, tid = threadIdx.x;
    float s = 0.f;
#pragma unroll
    for (int q = 0; q < 16; q++) s += pp[(size_t)(b * 16 + q) * D_ + tid];
    pooled[tid] = s * (1.f / T_);
    __syncthreads();
    if (tid < NC_) {
        float acc = bc[tid];
#pragma unroll 8
        for (int e = 0; e < D_; e++) acc = fmaf(pooled[e], Wc[e * NC_ + tid], acc);
        out[b * NC_ + tid] = acc;
    }
}

// =====================================================================
extern "C" void kernel_launch(void* const* d_in, const int* in_sizes, int n_in,
                              void* d_out, int out_size)
{
    const float* x     = (const float*)d_in[0];
    const float* W_in  = (const float*)d_in[1];
    const float* b_in  = (const float*)d_in[2];
    const float* Wv_a  = (const float*)d_in[3];
    const float* bv_a  = (const float*)d_in[4];
    const float* Wo_a  = (const float*)d_in[5];
    const float* bo_a  = (const float*)d_in[6];
    const float* ln1_g = (const float*)d_in[7];
    const float* ln1_b = (const float*)d_in[8];
    const float* pw1_w = (const float*)d_in[9];
    const float* pw1_b = (const float*)d_in[10];
    const float* dw_w  = (const float*)d_in[11];
    const float* dw_b  = (const float*)d_in[12];
    const float* bn_s  = (const float*)d_in[13];
    const float* bn_b  = (const float*)d_in[14];
    const float* pw2_w = (const float*)d_in[15];
    const float* pw2_b = (const float*)d_in[16];
    const float* Wk_t  = (const float*)d_in[17];
    const float* Wv_t  = (const float*)d_in[18];
    const float* Wq_t  = (const float*)d_in[19];
    const float* Wk_d  = (const float*)d_in[20];
    const float* Wv_d  = (const float*)d_in[21];
    const float* Wq_d  = (const float*)d_in[22];
    const float* ln2_g = (const float*)d_in[23];
    const float* ln2_b = (const float*)d_in[24];
    const float* Wc    = (const float*)d_in[25];
    const float* bc    = (const float*)d_in[26];
    float* out = (float*)d_out;

    float *xp, *x2, *hbuf, *g2p, *x3, *Kd, *Vd, *Qd, *Ed, *Fd, *Kt, *Vt, *Qt, *Et;
    float *Wao, *bao, *Wkqd, *Wkqt, *pp;
    cudaGetSymbolAddress((void**)&xp,   g_xp);
    cudaGetSymbolAddress((void**)&x2,   g_x2);
    cudaGetSymbolAddress((void**)&hbuf, g_h);
    cudaGetSymbolAddress((void**)&g2p,  g_g2);
    cudaGetSymbolAddress((void**)&x3,   g_x3);
    cudaGetSymbolAddress((void**)&Kd,   g_Kd);
    cudaGetSymbolAddress((void**)&Vd,   g_Vd);
    cudaGetSymbolAddress((void**)&Qd,   g_Qd);
    cudaGetSymbolAddress((void**)&Ed,   g_Ed);
    cudaGetSymbolAddress((void**)&Fd,   g_Fd);
    cudaGetSymbolAddress((void**)&Kt,   g_Kt);
    cudaGetSymbolAddress((void**)&Vt,   g_Vt);
    cudaGetSymbolAddress((void**)&Qt,   g_Qt);
    cudaGetSymbolAddress((void**)&Et,   g_Et);
    cudaGetSymbolAddress((void**)&Wao,  g_Wao);
    cudaGetSymbolAddress((void**)&bao,  g_bao);
    cudaGetSymbolAddress((void**)&Wkqd, g_Wkqd);
    cudaGetSymbolAddress((void**)&Wkqt, g_Wkqt);
    cudaGetSymbolAddress((void**)&pp,   g_pp);

    const int MMA3_SMEM = (2 * PLANE_A + 2 * PLANE_W) * 4;          // 210944
    const int X2_SMEM   = MMA3_SMEM + (ND_ * D_ * 2 + 256) * 4;     // +7168
    const int QKF_SMEM  = (192 * 33 + NT_ * D_ + 192 + 32 + 32 + 12) * 4;
    cudaFuncSetAttribute(mma_gemm, cudaFuncAttributeMaxDynamicSharedMemorySize, MMA3_SMEM);
    cudaFuncSetAttribute(mma_x2,   cudaFuncAttributeMaxDynamicSharedMemorySize, X2_SMEM);
    cudaFuncSetAttribute(mma_glu,  cudaFuncAttributeMaxDynamicSharedMemorySize, MMA3_SMEM);
    cudaFuncSetAttribute(qkfinal,  cudaFuncAttributeMaxDynamicSharedMemorySize, QKF_SMEM);

    // 1) weight folds (fp32)
    folds_kernel<<<28, 256>>>(Wv_a, Wo_a, bv_a, bo_a, Wk_d, Wq_d, Wk_t, Wq_t);
    // 2) xp = x @ W_in + b_in  (3xTF32)
    mma_gemm<<<96, 256, MMA3_SMEM>>>(xp, x, W_in, b_in, nullptr, MEL_, MEL_);
    // 3) delta K/V/Ktilde
    projKVQ<<<B_ * ND_, 192>>>(Kd, Vd, Qd, xp, Wk_d, Wv_d, Wkqd, ND_, 64);
    // 4) delta err + F
    rec_d_kernel<<<B_, 256>>>(Ed, Fd, Kd, Vd, Wao);
    // 5) x2 = xp + xp@Wao + bao + alpha@F  (3xTF32)
    mma_x2<<<96, 256, X2_SMEM>>>(x2, xp, Wao, bao, Qd, Fd);
    // 6) h = LN1(x2)
    ln_kernel<<<B_ * T_, 192>>>(hbuf, x2, ln1_g, ln1_b);
    // 7) g2 = SiLU(BN(dw(GLU(h@pw1+b))))  (3xTF32, two W halves)
    mma_glu<<<96, 256, MMA3_SMEM>>>(g2p, hbuf, pw1_w, pw1_b, dw_w, dw_b, bn_s, bn_b);
    // 8) x3 = x2 + g2@pw2 + b  (3xTF32)
    mma_gemm<<<96, 256, MMA3_SMEM>>>(x3, g2p, pw2_w, pw2_b, x2, D_, D_);
    // 9) theta K/V/Ktilde
    projKVQ<<<B_ * NT_, 192>>>(Kt, Vt, Qt, x3, Wk_t, Wv_t, Wkqt, NT_, 8);
    // 10) theta err recurrence
    rec_t_kernel<<<B_, 256>>>(Et, Kt, Vt);
    // 11) retrieval + LN2 -> partial pools
    qkfinal<<<B_ * 16, 192, QKF_SMEM>>>(x3, Qt, Et, ln2_g, ln2_b, pp);
    // 12) pool + classifier
    poolcls<<<B_, 192>>>(pp, Wc, bc, out);
}

// round 16
// speedup vs baseline: 1.1036x; 1.1036x over previous
#include <cuda_runtime.h>
#include <math.h>

#define B_   8
#define T_   256
#define MEL_ 128
#define D_   192
#define NC_  20
#define D2_  384
#define NT_  32
#define ND_  4
#define EPS_ 1e-5f

__device__ float g_xp [B_*T_*D_];
__device__ float g_x2 [B_*T_*D_];
__device__ float g_h  [B_*T_*D_];
__device__ float g_g2 [B_*T_*D_];
__device__ float g_x3 [B_*T_*D_];
__device__ float g_Kd [B_*ND_*D_];
__device__ float g_Vd [B_*ND_*D_];
__device__ float g_Qd [B_*ND_*D_];
__device__ float g_Ed [B_*ND_*D_];
__device__ float g_Kt [B_*NT_*D_];
__device__ float g_Vt [B_*NT_*D_];
__device__ float g_Qt [B_*NT_*D_];
__device__ float g_Et [B_*NT_*D_];
__device__ float g_Wao [D_*D_];
__device__ float g_bao [D_];
__device__ float g_Wkqd[D_*D_];
__device__ float g_Wkqt[D_*D_];
__device__ float g_pp [B_*16*D_];

__device__ __forceinline__ float cdv(int d) {
    const float L2A = -0.014499569695115089f;   // log2(0.99)
    const float L2E = -0.152003093445049970f;   // log2(0.90)
    float n = (float)(d + 1);
    return (exp2f(n * L2A) - exp2f(n * L2E)) * (0.1f / 0.09f);
}

// =================== 3xTF32 warp-MMA GEMM machinery ===================
#define AS_STRIDE 196
#define WS_STRIDE 72
#define PLANE_A (64 * AS_STRIDE)
#define PLANE_W (192 * WS_STRIDE)

__device__ __forceinline__ unsigned f2tf(float v) {
    unsigned r; asm("cvt.rna.tf32.f32 %0, %1;" : "=r"(r) : "f"(v)); return r;
}
__device__ __forceinline__ void mma8(float c[4], unsigned a0, unsigned a1, unsigned a2,
                                     unsigned a3, unsigned b0, unsigned b1) {
    asm("mma.sync.aligned.m16n8k8.row.col.f32.tf32.tf32.f32 "
        "{%0,%1,%2,%3},{%4,%5,%6,%7},{%8,%9},{%0,%1,%2,%3};"
        : "+f"(c[0]), "+f"(c[1]), "+f"(c[2]), "+f"(c[3])
        : "r"(a0), "r"(a1), "r"(a2), "r"(a3), "r"(b0), "r"(b1));
}
__device__ __forceinline__ void split2(float v, unsigned& hi, unsigned& lo) {
    hi = f2tf(v);
    lo = f2tf(v - __uint_as_float(hi));
}
__device__ __forceinline__ void fillA3(unsigned* Ahi, unsigned* Alo,
                                       const float* __restrict__ A, int ldA, int m0, int K) {
    int tid = threadIdx.x;
    int kq = K >> 2;
    for (int idx = tid; idx < 64 * kq; idx += 256) {
        int r = idx / kq, c4 = idx - r * kq;
        float4 v = *(const float4*)&A[(size_t)(m0 + r) * ldA + c4 * 4];
        uint4 h, l;
        split2(v.x, h.x, l.x); split2(v.y, h.y, l.y);
        split2(v.z, h.z, l.z); split2(v.w, h.w, l.w);
        *(uint4*)&Ahi[r * AS_STRIDE + c4 * 4] = h;
        *(uint4*)&Alo[r * AS_STRIDE + c4 * 4] = l;
    }
}
__device__ __forceinline__ void fillW3(unsigned* Whi, unsigned* Wlo,
                                       const float* __restrict__ W, int ldW, int col0, int K) {
    int tid = threadIdx.x;
    for (int idx = tid; idx < K * 16; idx += 256) {
        int k = idx >> 4, c4 = idx & 15;
        float4 v = *(const float4*)&W[(size_t)k * ldW + col0 + c4 * 4];
        uint4 h, l;
        split2(v.x, h.x, l.x); split2(v.y, h.y, l.y);
        split2(v.z, h.z, l.z); split2(v.w, h.w, l.w);
        *(uint4*)&Whi[k * WS_STRIDE + c4 * 4] = h;
        *(uint4*)&Wlo[k * WS_STRIDE + c4 * 4] = l;
    }
}
__device__ __forceinline__ void mma_core3(const unsigned* Ahi, const unsigned* Alo,
                                          const unsigned* Whi, const unsigned* Wlo,
                                          int K, float acc[4][4], int w, int lane) {
    int gid = lane >> 2, tig = lane & 3;
    int wr0 = (w & 3) * 16, wc0 = (w >> 2) * 32;
    for (int ks = 0; ks < K; ks += 8) {
        int i00 = (wr0 + gid) * AS_STRIDE + ks + tig;
        int i10 = (wr0 + gid + 8) * AS_STRIDE + ks + tig;
        unsigned ah0 = Ahi[i00], ah1 = Ahi[i10], ah2 = Ahi[i00 + 4], ah3 = Ahi[i10 + 4];
        unsigned al0 = Alo[i00], al1 = Alo[i10], al2 = Alo[i00 + 4], al3 = Alo[i10 + 4];
#pragma unroll
        for (int j = 0; j < 4; j++) {
            int b0i = (ks + tig) * WS_STRIDE + wc0 + j * 8 + gid;
            int b1i = (ks + tig + 4) * WS_STRIDE + wc0 + j * 8 + gid;
            unsigned bh0 = Whi[b0i], bh1 = Whi[b1i];
            unsigned bl0 = Wlo[b0i], bl1 = Wlo[b1i];
            mma8(acc[j], ah0, ah1, ah2, ah3, bh0, bh1);
            mma8(acc[j], ah0, ah1, ah2, ah3, bl0, bl1);
            mma8(acc[j], al0, al1, al2, al3, bh0, bh1);
        }
    }
}

// ---------------- generic 3xTF32 GEMM ----------------
__global__ void __launch_bounds__(256) mma_gemm(
    float* __restrict__ C, const float* __restrict__ A, const float* __restrict__ W,
    const float* __restrict__ bias, const float* __restrict__ res, int ldA, int K)
{
    extern __shared__ __align__(16) unsigned sh[];
    unsigned* Ahi = sh;
    unsigned* Alo = sh + PLANE_A;
    unsigned* Whi = sh + 2 * PLANE_A;
    unsigned* Wlo = Whi + PLANE_W;
    int blk = blockIdx.x;
    int m0 = (blk / 3) * 64, n0 = (blk % 3) * 64;
    int tid = threadIdx.x, w = tid >> 5, lane = tid & 31;
    fillA3(Ahi, Alo, A, ldA, m0, K);
    fillW3(Whi, Wlo, W, D_, n0, K);
    __syncthreads();
    float acc[4][4] = {};
    mma_core3(Ahi, Alo, Whi, Wlo, K, acc, w, lane);
    int gid = lane >> 2, tig = lane & 3;
    int wr0 = (w & 3) * 16, wc0 = (w >> 2) * 32;
#pragma unroll
    for (int j = 0; j < 4; j++) {
        int col = n0 + wc0 + j * 8 + 2 * tig;
        int r0 = m0 + wr0 + gid, r1 = r0 + 8;
        float b0 = bias ? bias[col] : 0.f, b1 = bias ? bias[col + 1] : 0.f;
        float2 o0 = { acc[j][0] + b0, acc[j][1] + b1 };
        float2 o1 = { acc[j][2] + b0, acc[j][3] + b1 };
        if (res) {
            float2 v0 = *(const float2*)&res[(size_t)r0 * D_ + col];
            float2 v1 = *(const float2*)&res[(size_t)r1 * D_ + col];
            o0.x += v0.x; o0.y += v0.y; o1.x += v1.x; o1.y += v1.y;
        }
        *(float2*)&C[(size_t)r0 * D_ + col] = o0;
        *(float2*)&C[(size_t)r1 * D_ + col] = o1;
    }
}

// ---------------- x2 3xTF32 GEMM: x2 = xp + xp@Wao + bao + alpha@F, F computed in-block ----------------
__global__ void __launch_bounds__(256) mma_x2(
    float* __restrict__ x2, const float* __restrict__ xp,
    const float* __restrict__ Wao, const float* __restrict__ bao,
    const float* __restrict__ Qd, const float* __restrict__ Ed)
{
    extern __shared__ __align__(16) unsigned sh[];
    unsigned* Ahi = sh;
    unsigned* Alo = sh + PLANE_A;
    unsigned* Whi = sh + 2 * PLANE_A;
    unsigned* Wlo = Whi + PLANE_W;
    float* sQ   = (float*)(Wlo + PLANE_W);   // [4*192]
    float* sEd  = sQ + ND_ * D_;             // [4*192]
    float* sF   = sEd + ND_ * D_;            // [4*64] (local cols n0..n0+63)
    float* alph = sF + ND_ * 64;             // [64][4]
    int blk = blockIdx.x;
    int m0 = (blk / 3) * 64, n0 = (blk % 3) * 64;
    int b = m0 >> 8;
    int tid = threadIdx.x, w = tid >> 5, lane = tid & 31;
    fillA3(Ahi, Alo, xp, D_, m0, D_);
    fillW3(Whi, Wlo, Wao, D_, n0, D_);
    for (int idx = tid; idx < ND_ * D_; idx += 256) {
        sQ[idx] = Qd[(size_t)b * ND_ * D_ + idx];
        sEd[idx] = Ed[(size_t)b * ND_ * D_ + idx];
    }
    __syncthreads();
    float acc[4][4] = {};
    mma_core3(Ahi, Alo, Whi, Wlo, D_, acc, w, lane);
    // alpha: thread (row = tid>>2, j = tid&3), xp reconstructed hi+lo
    {
        int row = tid >> 2, j = tid & 3;
        const float* qj = &sQ[j * D_];
        const unsigned* ah = &Ahi[row * AS_STRIDE];
        const unsigned* al = &Alo[row * AS_STRIDE];
        float s0 = 0.f, s1 = 0.f;
#pragma unroll 8
        for (int k = 0; k < D_; k += 2) {
            float v0 = __uint_as_float(ah[k])     + __uint_as_float(al[k]);
            float v1 = __uint_as_float(ah[k + 1]) + __uint_as_float(al[k + 1]);
            s0 = fmaf(v0, qj[k],     s0);
            s1 = fmaf(v1, qj[k + 1], s1);
        }
        float s = s0 + s1;
        int t = (m0 + row) & (T_ - 1), r = t >> 6;
        alph[row * 4 + j] = (j <= r) ? 0.5f * cdv(r - j) * s : 0.f;
    }
    // local F: thread (jj = tid>>6, c = tid&63); Wao[e][n0+c] from smem planes
    {
        int jj = tid >> 6, c = tid & 63;
        const float* er = &sEd[jj * D_];
        float a0 = er[n0 + c];
        float a1 = 0.f;
#pragma unroll 4
        for (int e = 0; e < D_; e += 2) {
            float w0 = __uint_as_float(Whi[e * WS_STRIDE + c]) + __uint_as_float(Wlo[e * WS_STRIDE + c]);
            float w1 = __uint_as_float(Whi[(e + 1) * WS_STRIDE + c]) + __uint_as_float(Wlo[(e + 1) * WS_STRIDE + c]);
            a0 = fmaf(er[e],     w0, a0);
            a1 = fmaf(er[e + 1], w1, a1);
        }
        sF[jj * 64 + c] = a0 + a1;
    }
    __syncthreads();
    int gid = lane >> 2, tig = lane & 3;
    int wr0 = (w & 3) * 16, wc0 = (w >> 2) * 32;
#pragma unroll
    for (int j = 0; j < 4; j++) {
        int col = n0 + wc0 + j * 8 + 2 * tig;
        int lc = col - n0;
        int lr0 = wr0 + gid, lr1 = lr0 + 8;
        int r0 = m0 + lr0, r1 = m0 + lr1;
        float2 v0 = *(const float2*)&xp[(size_t)r0 * D_ + col];
        float2 v1 = *(const float2*)&xp[(size_t)r1 * D_ + col];
        float o00 = acc[j][0] + bao[col] + v0.x;
        float o01 = acc[j][1] + bao[col + 1] + v0.y;
        float o10 = acc[j][2] + bao[col] + v1.x;
        float o11 = acc[j][3] + bao[col + 1] + v1.y;
#pragma unroll
        for (int jj = 0; jj < ND_; jj++) {
            float f0 = sF[jj * 64 + lc], f1 = sF[jj * 64 + lc + 1];
            float a0 = alph[lr0 * 4 + jj], a1 = alph[lr1 * 4 + jj];
            o00 = fmaf(a0, f0, o00); o01 = fmaf(a0, f1, o01);
            o10 = fmaf(a1, f0, o10); o11 = fmaf(a1, f1, o11);
        }
        float2 w0 = {o00, o01}, w1 = {o10, o11};
        *(float2*)&x2[(size_t)r0 * D_ + col] = w0;
        *(float2*)&x2[(size_t)r1 * D_ + col] = w1;
    }
}

// ---------------- glu 3xTF32 (two W halves sequentially) + GLU/dw/BN/SiLU ----------------
__global__ void __launch_bounds__(256) mma_glu(
    float* __restrict__ outp, const float* __restrict__ A, const float* __restrict__ W,
    const float* __restrict__ bias,
    const float* __restrict__ dw, const float* __restrict__ db,
    const float* __restrict__ bs, const float* __restrict__ bb)
{
    extern __shared__ __align__(16) unsigned sh[];
    unsigned* Ahi = sh;
    unsigned* Alo = sh + PLANE_A;
    unsigned* Whi = sh + 2 * PLANE_A;
    unsigned* Wlo = Whi + PLANE_W;
    int blk = blockIdx.x;
    int m0 = (blk / 3) * 64, n0 = (blk % 3) * 64;
    int tid = threadIdx.x, w = tid >> 5, lane = tid & 31;
    fillA3(Ahi, Alo, A, D_, m0, D_);
    fillW3(Whi, Wlo, W, D2_, n0, D_);
    __syncthreads();
    float cA[4][4] = {}, cG[4][4] = {};
    mma_core3(Ahi, Alo, Whi, Wlo, D_, cA, w, lane);
    __syncthreads();
    fillW3(Whi, Wlo, W, D2_, D_ + n0, D_);
    __syncthreads();
    mma_core3(Ahi, Alo, Whi, Wlo, D_, cG, w, lane);
    int gid = lane >> 2, tig = lane & 3;
    int wr0 = (w & 3) * 16, wc0 = (w >> 2) * 32;
#pragma unroll
    for (int j = 0; j < 4; j++) {
        int col = n0 + wc0 + j * 8 + 2 * tig;
        int r0 = m0 + wr0 + gid, r1 = r0 + 8;
#pragma unroll
        for (int half = 0; half < 2; half++) {
            int row = half ? r1 : r0;
            float va = (half ? cA[j][2] : cA[j][0]);
            float vb = (half ? cA[j][3] : cA[j][1]);
            float ga = (half ? cG[j][2] : cG[j][0]);
            float gb = (half ? cG[j][3] : cG[j][1]);
            float2 o;
#pragma unroll
            for (int u = 0; u < 2; u++) {
                int cc = col + u;
                float a = (u ? vb : va) + bias[cc];
                float g = (u ? gb : ga) + bias[D_ + cc];
                float h = a * (1.f / (1.f + expf(-g)));
                h = h * dw[cc] + db[cc];
                h = h * bs[cc] + bb[cc];
                h = h * (1.f / (1.f + expf(-h)));
                (u ? o.y : o.x) = h;
            }
            *(float2*)&outp[(size_t)row * D_ + col] = o;
        }
    }
}

// =================== fp32 pieces ===================
__device__ __forceinline__ void dev_gemm_tile(float* sh,
    const float* __restrict__ A, int ldA, const float* __restrict__ W, int ldW, bool transB,
    const float* __restrict__ bias, const float* __restrict__ res, float* __restrict__ C, int ldC,
    int m0, int n0, int K)
{
    float (*As)[68] = (float (*)[68])sh;
    float (*Ws)[64] = (float (*)[64])(sh + 16 * 68);
    int tid = threadIdx.x;
    int tx = tid & 15, ty = tid >> 4;
    float c[4][4] = {};
    for (int k0 = 0; k0 < K; k0 += 16) {
        {
            int arow = tid >> 2, acol = (tid & 3) * 4;
            float4 v = *(const float4*)&A[(size_t)(m0 + arow) * ldA + k0 + acol];
            As[acol + 0][arow] = v.x; As[acol + 1][arow] = v.y;
            As[acol + 2][arow] = v.z; As[acol + 3][arow] = v.w;
        }
        {
            int wrow = tid >> 4, wcol = (tid & 15) * 4;
            if (transB) {
#pragma unroll
                for (int u = 0; u < 4; u++)
                    Ws[wrow][wcol + u] = W[(size_t)(n0 + wcol + u) * ldW + k0 + wrow];
            } else {
                *(float4*)&Ws[wrow][wcol] = *(const float4*)&W[(size_t)(k0 + wrow) * ldW + n0 + wcol];
            }
        }
        __syncthreads();
#pragma unroll
        for (int kk = 0; kk < 16; kk++) {
            float4 af = *(const float4*)&As[kk][ty * 4];
            float4 bf = *(const float4*)&Ws[kk][tx * 4];
            float a4[4] = {af.x, af.y, af.z, af.w};
            float b4[4] = {bf.x, bf.y, bf.z, bf.w};
#pragma unroll
            for (int i = 0; i < 4; i++)
#pragma unroll
                for (int j = 0; j < 4; j++) c[i][j] = fmaf(a4[i], b4[j], c[i][j]);
        }
        __syncthreads();
    }
#pragma unroll
    for (int i = 0; i < 4; i++) {
        int row = m0 + ty * 4 + i, col = n0 + tx * 4;
        float4 o; float* po = &o.x;
#pragma unroll
        for (int j = 0; j < 4; j++) {
            float v = c[i][j];
            if (bias) v += bias[col + j];
            if (res)  v += res[(size_t)row * ldC + col + j];
            po[j] = v;
        }
        *(float4*)&C[(size_t)row * ldC + col] = o;
    }
}

__global__ void __launch_bounds__(256) folds_kernel(
    const float* __restrict__ Wv_a, const float* __restrict__ Wo_a,
    const float* __restrict__ bv_a, const float* __restrict__ bo_a,
    const float* __restrict__ Wk_d, const float* __restrict__ Wq_d,
    const float* __restrict__ Wk_t, const float* __restrict__ Wq_t)
{
    __shared__ __align__(16) float sh[16 * 68 + 16 * 64];
    int blk = blockIdx.x, tid = threadIdx.x;
    if (blk < 9) {
        dev_gemm_tile(sh, Wv_a, D_, Wo_a, D_, false, nullptr, nullptr, g_Wao, D_,
                      (blk / 3) * 64, (blk % 3) * 64, D_);
    } else if (blk < 18) {
        int p = blk - 9;
        dev_gemm_tile(sh, Wk_d, D_, Wq_d, D_, true, nullptr, nullptr, g_Wkqd, D_,
                      (p / 3) * 64, (p % 3) * 64, D_);
    } else if (blk < 27) {
        int p = blk - 18;
        dev_gemm_tile(sh, Wk_t, D_, Wq_t, D_, true, nullptr, nullptr, g_Wkqt, D_,
                      (p / 3) * 64, (p % 3) * 64, D_);
    } else {
        if (tid < D_) {
            float s = bo_a[tid];
#pragma unroll 8
            for (int e = 0; e < D_; e++) s = fmaf(bv_a[e], Wo_a[e * D_ + tid], s);
            g_bao[tid] = s;
        }
    }
}

__global__ void __launch_bounds__(192) projKVQ(
    float* __restrict__ Ko, float* __restrict__ Vo, float* __restrict__ Qo,
    const float* __restrict__ A, const float* __restrict__ Wk,
    const float* __restrict__ Wv, const float* __restrict__ Wkq, int nUpd, int chunk)
{
    __shared__ float sa[D_];
    int blk = blockIdx.x;
    int b = blk / nUpd, i = blk % nUpd;
    int tid = threadIdx.x;
    sa[tid] = A[(size_t)(b * T_ + i * chunk) * D_ + tid];
    __syncthreads();
    if (tid < 144) {
        int gsel = tid / 48, q = tid % 48;
        const float* W = (gsel == 0) ? Wk : (gsel == 1) ? Wv : Wkq;
        float ax = 0.f, ay = 0.f, az = 0.f, aw = 0.f;
#pragma unroll 16
        for (int kk = 0; kk < D_; kk++) {
            float a = sa[kk];
            float4 wv = *(const float4*)&W[kk * D_ + 4 * q];
            ax = fmaf(a, wv.x, ax); ay = fmaf(a, wv.y, ay);
            az = fmaf(a, wv.z, az); aw = fmaf(a, wv.w, aw);
        }
        float* O = (gsel == 0) ? Ko : (gsel == 1) ? Vo : Qo;
        float4 o = {ax, ay, az, aw};
        *(float4*)&O[(size_t)blk * D_ + 4 * q] = o;
    }
}

// ---------------- rec_d: delta err chain only, K+V in smem ----------------
__global__ void __launch_bounds__(256) rec_d_kernel(
    float* __restrict__ ERR, const float* __restrict__ Kmat, const float* __restrict__ Vmat)
{
    __shared__ float sK[ND_][D_ + 1];
    __shared__ float sV[ND_][D_];
    __shared__ float Acf[ND_][ND_];
    int b = blockIdx.x, tid = threadIdx.x;
    for (int idx = tid; idx < ND_ * D_; idx += 256) {
        int r = idx / D_, c = idx % D_;
        sK[r][c] = Kmat[(size_t)b * ND_ * D_ + idx];
        sV[r][c] = Vmat[(size_t)b * ND_ * D_ + idx];
    }
    __syncthreads();
    if (tid < 6) {
        const int pi[6] = {1, 2, 2, 3, 3, 3};
        const int pj[6] = {0, 0, 1, 0, 1, 2};
        int i = pi[tid], j = pj[tid];
        float s0 = 0.f, s1 = 0.f;
#pragma unroll 8
        for (int kk = 0; kk < D_; kk += 2) {
            s0 = fmaf(sK[j][kk],     sK[i][kk],     s0);
            s1 = fmaf(sK[j][kk + 1], sK[i][kk + 1], s1);
        }
        Acf[j][i] = cdv(i - 1 - j) * (s0 + s1);
    }
    __syncthreads();
    if (tid < D_) {
        float err[ND_];
#pragma unroll
        for (int i = 0; i < ND_; i++) {
            float s = sV[i][tid];
#pragma unroll
            for (int j = 0; j < i; j++) s -= Acf[j][i] * err[j];
            err[i] = s;
            ERR[(size_t)(b * ND_ + i) * D_ + tid] = s;
        }
    }
}

__global__ void __launch_bounds__(192) ln_kernel(
    float* __restrict__ outp, const float* __restrict__ in,
    const float* __restrict__ g, const float* __restrict__ bta)
{
    __shared__ float red[2][6];
    int row = blockIdx.x, e = threadIdx.x;
    float v = in[(size_t)row * D_ + e];
    float s = v, s2 = v * v;
#pragma unroll
    for (int o = 16; o > 0; o >>= 1) {
        s  += __shfl_xor_sync(~0u, s,  o);
        s2 += __shfl_xor_sync(~0u, s2, o);
    }
    int w = e >> 5, l = e & 31;
    if (l == 0) { red[0][w] = s; red[1][w] = s2; }
    __syncthreads();
    float ts = 0.f, ts2 = 0.f;
#pragma unroll
    for (int i = 0; i < 6; i++) { ts += red[0][i]; ts2 += red[1][i]; }
    float m = ts / D_;
    float var = ts2 / D_ - m * m;
    outp[(size_t)row * D_ + e] = (v - m) * rsqrtf(var + EPS_) * g[e] + bta[e];
}

// ---------------- rec_t: theta err chain, K+V in dynamic smem ----------------
__global__ void __launch_bounds__(256) rec_t_kernel(
    float* __restrict__ ERR, const float* __restrict__ Kmat, const float* __restrict__ Vmat)
{
    extern __shared__ __align__(16) float shr[];
    float* sK  = shr;                        // [32][193]
    float* sV  = sK + NT_ * (D_ + 1);        // [32][192]
    float* Acf = sV + NT_ * D_;              // [32][32]
    float* cd  = Acf + NT_ * NT_;            // [32]
    int b = blockIdx.x, tid = threadIdx.x;
    if (tid < NT_) cd[tid] = cdv(tid);
    for (int idx = tid; idx < NT_ * D_; idx += 256) {
        int r = idx / D_, c = idx % D_;
        sK[r * (D_ + 1) + c] = Kmat[(size_t)b * NT_ * D_ + idx];
        sV[idx] = Vmat[(size_t)b * NT_ * D_ + idx];
    }
    __syncthreads();
    const int NP = NT_ * (NT_ - 1) / 2;
    for (int p = tid; p < NP; p += 256) {
        int i = (int)((1.0f + sqrtf(1.0f + 8.0f * (float)p)) * 0.5f);
        while (i * (i - 1) / 2 > p) i--;
        while ((i + 1) * i / 2 <= p) i++;
        int j = p - i * (i - 1) / 2;
        float s0 = 0.f, s1 = 0.f;
        const float* kj = &sK[j * (D_ + 1)];
        const float* ki = &sK[i * (D_ + 1)];
#pragma unroll 8
        for (int kk = 0; kk < D_; kk += 2) {
            s0 = fmaf(kj[kk],     ki[kk],     s0);
            s1 = fmaf(kj[kk + 1], ki[kk + 1], s1);
        }
        Acf[j * NT_ + i] = cd[i - 1 - j] * (s0 + s1);
    }
    __syncthreads();
    if (tid < D_) {
        float err[NT_];
#pragma unroll
        for (int i = 0; i < NT_; i++) {
            float a0 = 0.f, a1 = 0.f;
#pragma unroll
            for (int j = 0; j < i; j++) {
                if (j & 1) a1 = fmaf(Acf[j * NT_ + i], err[j], a1);
                else       a0 = fmaf(Acf[j * NT_ + i], err[j], a0);
            }
            err[i] = sV[i * D_ + tid] - a0 - a1;
            ERR[(size_t)(b * NT_ + i) * D_ + tid] = err[i];
        }
    }
}

__global__ void __launch_bounds__(192) qkfinal(
    const float* __restrict__ x3, const float* __restrict__ Kt, const float* __restrict__ Et,
    const float* __restrict__ g2, const float* __restrict__ b2, float* __restrict__ pp)
{
    extern __shared__ __align__(16) float shq[];
    float (*sKT)[33] = (float (*)[33])shq;
    float* sEt = shq + 192 * 33;
    float* red = sEt + NT_ * D_;
    float* alpha = red + 192;
    float* cd = alpha + 32;
    float* lred = cd + 32;
    int blk = blockIdx.x;
    int b = blk >> 4, tc = blk & 15, t0 = tc * 16;
    int tid = threadIdx.x;
    if (tid < NT_) cd[tid] = cdv(tid);
    for (int idx = tid; idx < NT_ * D_; idx += 192) {
        int j = idx / D_, e = idx % D_;
        sKT[e][j] = Kt[(size_t)(b * NT_ + j) * D_ + e];
        sEt[idx] = Et[(size_t)b * NT_ * D_ + idx];
    }
    __syncthreads();
    int j = tid & 31, g = tid >> 5;
    float ps = 0.f;
    for (int tt = 0; tt < 16; tt++) {
        int t = t0 + tt, row = b * T_ + t, r = t >> 3;
        {
            const float* qr = x3 + (size_t)row * D_;
            float part = 0.f;
#pragma unroll
            for (int u = 0; u < 32; u++) part = fmaf(qr[g * 32 + u], sKT[g * 32 + u][j], part);
            red[j * 6 + g] = part;
        }
        __syncthreads();
        if (tid < NT_) {
            float s = 0.f;
#pragma unroll
            for (int gg = 0; gg < 6; gg++) s += red[tid * 6 + gg];
            alpha[tid] = (tid <= r) ? cd[r - tid] * s : 0.f;
        }
        __syncthreads();
        float s = 0.f;
        for (int jj = 0; jj <= r; jj++) s = fmaf(alpha[jj], sEt[jj * D_ + tid], s);
        float x4 = x3[(size_t)row * D_ + tid] + 0.5f * s;
        float sm = x4, s2 = x4 * x4;
#pragma unroll
        for (int o = 16; o > 0; o >>= 1) {
            sm += __shfl_xor_sync(~0u, sm, o);
            s2 += __shfl_xor_sync(~0u, s2, o);
        }
        if ((tid & 31) == 0) { lred[tid >> 5] = sm; lred[6 + (tid >> 5)] = s2; }
        __syncthreads();
        float ts = 0.f, ts2 = 0.f;
#pragma unroll
        for (int i = 0; i < 6; i++) { ts += lred[i]; ts2 += lred[6 + i]; }
        float m = ts / D_;
        float var = ts2 / D_ - m * m;
        ps += (x4 - m) * rsqrtf(var + EPS_) * g2[tid] + b2[tid];
        __syncthreads();
    }
    pp[(size_t)(b * 16 + tc) * D_ + tid] = ps;
}

__global__ void __launch_bounds__(192) poolcls(
    const float* __restrict__ pp, const float* __restrict__ Wc,
    const float* __restrict__ bc, float* __restrict__ out)
{
    __shared__ float pooled[D_];
    int b = blockIdx.x, tid = threadIdx.x;
    float s = 0.f;
#pragma unroll
    for (int q = 0; q < 16; q++) s += pp[(size_t)(b * 16 + q) * D_ + tid];
    pooled[tid] = s * (1.f / T_);
    __syncthreads();
    if (tid < NC_) {
        float acc = bc[tid];
#pragma unroll 8
        for (int e = 0; e < D_; e++) acc = fmaf(pooled[e], Wc[e * NC_ + tid], acc);
        out[b * NC_ + tid] = acc;
    }
}

// =====================================================================
extern "C" void kernel_launch(void* const* d_in, const int* in_sizes, int n_in,
                              void* d_out, int out_size)
{
    const float* x     = (const float*)d_in[0];
    const float* W_in  = (const float*)d_in[1];
    const float* b_in  = (const float*)d_in[2];
    const float* Wv_a  = (const float*)d_in[3];
    const float* bv_a  = (const float*)d_in[4];
    const float* Wo_a  = (const float*)d_in[5];
    const float* bo_a  = (const float*)d_in[6];
    const float* ln1_g = (const float*)d_in[7];
    const float* ln1_b = (const float*)d_in[8];
    const float* pw1_w = (const float*)d_in[9];
    const float* pw1_b = (const float*)d_in[10];
    const float* dw_w  = (const float*)d_in[11];
    const float* dw_b  = (const float*)d_in[12];
    const float* bn_s  = (const float*)d_in[13];
    const float* bn_b  = (const float*)d_in[14];
    const float* pw2_w = (const float*)d_in[15];
    const float* pw2_b = (const float*)d_in[16];
    const float* Wk_t  = (const float*)d_in[17];
    const float* Wv_t  = (const float*)d_in[18];
    const float* Wq_t  = (const float*)d_in[19];
    const float* Wk_d  = (const float*)d_in[20];
    const float* Wv_d  = (const float*)d_in[21];
    const float* Wq_d  = (const float*)d_in[22];
    const float* ln2_g = (const float*)d_in[23];
    const float* ln2_b = (const float*)d_in[24];
    const float* Wc    = (const float*)d_in[25];
    const float* bc    = (const float*)d_in[26];
    float* out = (float*)d_out;

    float *xp, *x2, *hbuf, *g2p, *x3, *Kd, *Vd, *Qd, *Ed, *Kt, *Vt, *Qt, *Et;
    float *Wao, *bao, *Wkqd, *Wkqt, *pp;
    cudaGetSymbolAddress((void**)&xp,   g_xp);
    cudaGetSymbolAddress((void**)&x2,   g_x2);
    cudaGetSymbolAddress((void**)&hbuf, g_h);
    cudaGetSymbolAddress((void**)&g2p,  g_g2);
    cudaGetSymbolAddress((void**)&x3,   g_x3);
    cudaGetSymbolAddress((void**)&Kd,   g_Kd);
    cudaGetSymbolAddress((void**)&Vd,   g_Vd);
    cudaGetSymbolAddress((void**)&Qd,   g_Qd);
    cudaGetSymbolAddress((void**)&Ed,   g_Ed);
    cudaGetSymbolAddress((void**)&Kt,   g_Kt);
    cudaGetSymbolAddress((void**)&Vt,   g_Vt);
    cudaGetSymbolAddress((void**)&Qt,   g_Qt);
    cudaGetSymbolAddress((void**)&Et,   g_Et);
    cudaGetSymbolAddress((void**)&Wao,  g_Wao);
    cudaGetSymbolAddress((void**)&bao,  g_bao);
    cudaGetSymbolAddress((void**)&Wkqd, g_Wkqd);
    cudaGetSymbolAddress((void**)&Wkqt, g_Wkqt);
    cudaGetSymbolAddress((void**)&pp,   g_pp);

    const int MMA3_SMEM = (2 * PLANE_A + 2 * PLANE_W) * 4;                       // 210944
    const int X2_SMEM   = MMA3_SMEM + (ND_ * D_ * 2 + ND_ * 64 + 256) * 4;       // +8192
    const int RECT_SMEM = (NT_ * (D_ + 1) + NT_ * D_ + NT_ * NT_ + NT_) * 4;     // 53504
    const int QKF_SMEM  = (192 * 33 + NT_ * D_ + 192 + 32 + 32 + 12) * 4;
    cudaFuncSetAttribute(mma_gemm,     cudaFuncAttributeMaxDynamicSharedMemorySize, MMA3_SMEM);
    cudaFuncSetAttribute(mma_x2,       cudaFuncAttributeMaxDynamicSharedMemorySize, X2_SMEM);
    cudaFuncSetAttribute(mma_glu,      cudaFuncAttributeMaxDynamicSharedMemorySize, MMA3_SMEM);
    cudaFuncSetAttribute(rec_t_kernel, cudaFuncAttributeMaxDynamicSharedMemorySize, RECT_SMEM);
    cudaFuncSetAttribute(qkfinal,      cudaFuncAttributeMaxDynamicSharedMemorySize, QKF_SMEM);

    // 1) weight folds (fp32)
    folds_kernel<<<28, 256>>>(Wv_a, Wo_a, bv_a, bo_a, Wk_d, Wq_d, Wk_t, Wq_t);
    // 2) xp = x @ W_in + b_in  (3xTF32)
    mma_gemm<<<96, 256, MMA3_SMEM>>>(xp, x, W_in, b_in, nullptr, MEL_, MEL_);
    // 3) delta K/V/Ktilde
    projKVQ<<<B_ * ND_, 192>>>(Kd, Vd, Qd, xp, Wk_d, Wv_d, Wkqd, ND_, 64);
    // 4) delta err
    rec_d_kernel<<<B_, 256>>>(Ed, Kd, Vd);
    // 5) x2 = xp + xp@Wao + bao + alpha@F  (3xTF32; F computed in-block)
    mma_x2<<<96, 256, X2_SMEM>>>(x2, xp, Wao, bao, Qd, Ed);
    // 6) h = LN1(x2)
    ln_kernel<<<B_ * T_, 192>>>(hbuf, x2, ln1_g, ln1_b);
    // 7) g2 = SiLU(BN(dw(GLU(h@pw1+b))))  (3xTF32)
    mma_glu<<<96, 256, MMA3_SMEM>>>(g2p, hbuf, pw1_w, pw1_b, dw_w, dw_b, bn_s, bn_b);
    // 8) x3 = x2 + g2@pw2 + b  (3xTF32)
    mma_gemm<<<96, 256, MMA3_SMEM>>>(x3, g2p, pw2_w, pw2_b, x2, D_, D_);
    // 9) theta K/V/Ktilde
    projKVQ<<<B_ * NT_, 192>>>(Kt, Vt, Qt, x3, Wk_t, Wv_t, Wkqt, NT_, 8);
    // 10) theta err recurrence (K+V smem)
    rec_t_kernel<<<B_, 256, RECT_SMEM>>>(Et, Kt, Vt);
    // 11) retrieval + LN2 -> partial pools
    qkfinal<<<B_ * 16, 192, QKF_SMEM>>>(x3, Qt, Et, ln2_g, ln2_b, pp);
    // 12) pool + classifier
    poolcls<<<B_, 192>>>(pp, Wc, bc, out);
}